// round 10
// baseline (speedup 1.0000x reference)
#include <cuda_runtime.h>
#include <cstdint>

#define BB 32
#define T_IN 512
#define NT 426
#define NC 1629          // 543*3
#define JF 53
#define XPART ((size_t)BB * NT * NC)   // 22,206,528
#define NCHUNK 7         // 7*256 = 1792 >= 1629

// ---- device scratch ----
__device__ int g_mode;
__device__ int g_K[BB];
__device__ int g_kept[BB][NT];

__device__ __forceinline__ bool read_bool_m(const void* p, int i, int m) {
    if (m == 0) return ((const unsigned char*)p)[i] != 0;
    if (m == 1) return ((const int*)p)[i] != 0;
    return ((const float*)p)[i] != 0.0f;
}

// One block per batch: dtype detect (128-word window, unambiguous across
// uint8/int32/float32 bool layouts) + warp-ballot prefix scan -> kept list.
__global__ __launch_bounds__(448) void scan_kernel(const void* __restrict__ keep) {
    __shared__ int s_bad, s_anyf, s_mode;
    __shared__ int wsum[14];

    int b = blockIdx.x;
    int t = threadIdx.x;                 // 448 threads, 14 warps

    if (t == 0) { s_bad = 0; s_anyf = 0; }
    __syncthreads();
    if (t < 128) {
        unsigned v = ((const unsigned*)keep)[t];
        if (v != 0u && v != 1u) atomicOr(&s_bad, 1);
        if (v == 0x3F800000u)   atomicOr(&s_anyf, 1);
    }
    __syncthreads();
    if (t == 0) {
        s_mode = s_bad ? (s_anyf ? 2 : 0) : 1;
        g_mode = s_mode;                 // all blocks write the same value
    }
    __syncthreads();
    int m = s_mode;

    bool kb = (t < NT) ? read_bool_m(keep, b * NT + t, m) : false;
    unsigned bal = __ballot_sync(0xFFFFFFFFu, kb);
    int lane = t & 31, wid = t >> 5;
    int pre = __popc(bal & ((1u << lane) - 1u));
    if (lane == 0) wsum[wid] = __popc(bal);
    __syncthreads();
    int base = 0;
    for (int i = 0; i < wid; i++) base += wsum[i];
    if (kb) g_kept[b][base + pre] = t;
    if (t == 0) {
        int K = 0;
        for (int i = 0; i < 14; i++) K += wsum[i];
        g_K[b] = K;
    }
}

// One block per (b,t). Thread 0 builds the (row, weight) list WHILE the other
// threads load noise/spatial into accumulators; then a software-pipelined
// streaming pass: out[b,t,:] = sum_i w_i * x[b,row_i,:] + noise*.01 + sp*.005.
__global__ __launch_bounds__(256, 6) void fused_kernel(
    const float* __restrict__ x,
    const void*  __restrict__ mask,
    const void*  __restrict__ keep,
    const float* __restrict__ bj,
    const float* __restrict__ noise,
    const float* __restrict__ sp,
    float* __restrict__ out)
{
    __shared__ int   srows[8];
    __shared__ float sw[8];
    __shared__ int   snum;

    const int bt  = blockIdx.x;
    const int b   = bt / NT;
    const int t   = bt - b * NT;
    const int tid = threadIdx.x;

    const float* nz = noise + (size_t)bt * NC;
    const float* sb = sp    + (size_t)b * NC;
    float*       ob = out   + (size_t)bt * NC;
    const float* xb = x     + (size_t)b * T_IN * NC;

    // ---- setup on thread 0 (overlapped with noise loads below) ----
    if (tid == 0) {
        int m = g_mode;
        int K = g_K[b];
        bool kb = read_bool_m(keep, bt, m);

        // mask output
        int nidx = (int)floorf((float)t * (512.0f / 426.0f));
        if (nidx > T_IN - 1) nidx = T_IN - 1;
        bool mo = read_bool_m(mask, b * T_IN + nidx, m) && kb;
        out[XPART + (size_t)bt] = mo ? 1.0f : 0.0f;

        // jitter (scale-then-lerp matches reference rounding)
        float jit = 0.0f;
        if (t > 0) {
            float sj = (float)t * (52.0f / 425.0f);
            int ij = (int)floorf(sj);
            if (ij > JF - 2) ij = JF - 2;
            if (ij < 0) ij = 0;
            float fj = sj - (float)ij;
            float j0 = bj[b * JF + ij]     * 0.02f;
            float j1 = bj[b * JF + ij + 1] * 0.02f;
            jit = j0 * (1.0f - fj) + j1 * fj;
        }

        int   rows[8];
        float wv[8];
        int n = 0;

        auto push = [&](int r, float w) {
            for (int i = 0; i < n; i++)
                if (rows[i] == r) { wv[i] += w; return; }
            rows[n] = r; wv[n] = w; n++;
        };
        auto add_x1 = [&](int tau, float c) {
            float s = (float)tau * (511.0f / 425.0f);
            int i0 = (int)floorf(s);
            if (i0 > T_IN - 2) i0 = T_IN - 2;
            if (i0 < 0) i0 = 0;
            float f = s - (float)i0;
            push(i0,     c * (1.0f - f));
            push(i0 + 1, c * f);
        };
        auto add_x2 = [&](int tau, float c) {
            if (read_bool_m(keep, b * NT + tau, m)) {
                add_x1(tau, c);
            } else {
                float s = ((float)tau * (float)(K - 1)) / 425.0f;
                int r0 = (int)floorf(s);
                if (r0 > K - 2) r0 = K - 2;
                if (r0 < 0) r0 = 0;
                float fd = s - (float)r0;
                add_x1(g_kept[b][r0],     c * (1.0f - fd));
                add_x1(g_kept[b][r0 + 1], c * fd);
            }
        };

        if (t == 0) {
            add_x2(0, 1.0f);
        } else {
            add_x2(t,     1.0f + jit);
            add_x2(t - 1, -jit);
        }
        snum = n;
        #pragma unroll
        for (int i = 0; i < 8; i++) {
            srows[i] = (i < n) ? rows[i] : 0;
            sw[i]    = (i < n) ? wv[i]   : 0.0f;
        }
    }

    // ---- all threads: noise + spatial into accumulators (independent of setup) ----
    float acc[NCHUNK];
    #pragma unroll
    for (int k = 0; k < NCHUNK; k++) {
        int e = tid + k * 256;
        acc[k] = (e < NC) ? fmaf(__ldcs(nz + e), 0.01f, sb[e] * 0.005f) : 0.0f;
    }
    __syncthreads();

    // ---- software-pipelined x pass: prefetch row i+1 while FMAing row i ----
    const int n = snum;
    float cur[NCHUNK];
    {
        const float* xr = xb + (size_t)srows[0] * NC;
        #pragma unroll
        for (int k = 0; k < NCHUNK; k++) {
            int e = tid + k * 256;
            cur[k] = (e < NC) ? __ldg(xr + e) : 0.0f;
        }
    }
    #pragma unroll 1
    for (int i = 0; i < n; i++) {
        float nxt[NCHUNK];
        if (i + 1 < n) {
            const float* xr = xb + (size_t)srows[i + 1] * NC;
            #pragma unroll
            for (int k = 0; k < NCHUNK; k++) {
                int e = tid + k * 256;
                nxt[k] = (e < NC) ? __ldg(xr + e) : 0.0f;
            }
        }
        float w = sw[i];
        #pragma unroll
        for (int k = 0; k < NCHUNK; k++)
            acc[k] = fmaf(w, cur[k], acc[k]);
        if (i + 1 < n) {
            #pragma unroll
            for (int k = 0; k < NCHUNK; k++)
                cur[k] = nxt[k];
        }
    }

    #pragma unroll
    for (int k = 0; k < NCHUNK; k++) {
        int e = tid + k * 256;
        if (e < NC) __stcs(ob + e, acc[k]);
    }
}

extern "C" void kernel_launch(void* const* d_in, const int* in_sizes, int n_in,
                              void* d_out, int out_size) {
    const float* x     = (const float*)d_in[0];
    const void*  mask  = d_in[1];
    const void*  keep  = d_in[2];
    const float* bj    = (const float*)d_in[3];
    const float* noise = (const float*)d_in[4];
    const float* sp    = (const float*)d_in[5];
    float* out = (float*)d_out;

    scan_kernel<<<BB, 448>>>(keep);
    fused_kernel<<<BB * NT, 256>>>(x, mask, keep, bj, noise, sp, out);
}

// round 14
// speedup vs baseline: 1.4468x; 1.4468x over previous
#include <cuda_runtime.h>
#include <cstdint>

#define BB 32
#define T_IN 512
#define NT 426
#define NC 1629          // 543*3
#define JF 53
#define XPART ((size_t)BB * NT * NC)   // 22,206,528
#define NCHUNK 7         // 7*256 = 1792 >= 1629

// ---- device scratch (SoA for coalesced access) ----
__device__ int   g_mode;
__device__ int   g_K[BB];
__device__ int   g_kept[BB][NT];
__device__ int   g_n[BB * NT];
__device__ int   g_rows[8][BB * NT];
__device__ float g_w[8][BB * NT];

__device__ __forceinline__ bool read_bool_m(const void* p, int i, int m) {
    if (m == 0) return ((const unsigned char*)p)[i] != 0;
    if (m == 1) return ((const int*)p)[i] != 0;
    return ((const float*)p)[i] != 0.0f;
}

// One block per batch: dtype detect (128-word window, unambiguous across
// uint8/int32/float32 bool layouts) + warp-ballot prefix scan -> kept list.
__global__ __launch_bounds__(448) void scan_kernel(const void* __restrict__ keep) {
    __shared__ int s_bad, s_anyf, s_mode;
    __shared__ int wsum[14];

    int b = blockIdx.x;
    int t = threadIdx.x;                 // 448 threads, 14 warps

    if (t == 0) { s_bad = 0; s_anyf = 0; }
    __syncthreads();
    if (t < 128) {
        unsigned v = ((const unsigned*)keep)[t];
        if (v != 0u && v != 1u) atomicOr(&s_bad, 1);
        if (v == 0x3F800000u)   atomicOr(&s_anyf, 1);
    }
    __syncthreads();
    if (t == 0) {
        s_mode = s_bad ? (s_anyf ? 2 : 0) : 1;
        g_mode = s_mode;                 // all blocks write the same value
    }
    __syncthreads();
    int m = s_mode;

    bool kb = (t < NT) ? read_bool_m(keep, b * NT + t, m) : false;
    unsigned bal = __ballot_sync(0xFFFFFFFFu, kb);
    int lane = t & 31, wid = t >> 5;
    int pre = __popc(bal & ((1u << lane) - 1u));
    if (lane == 0) wsum[wid] = __popc(bal);
    __syncthreads();
    int base = 0;
    for (int i = 0; i < wid; i++) base += wsum[i];
    if (kb) g_kept[b][base + pre] = t;
    if (t == 0) {
        int K = 0;
        for (int i = 0; i < 14; i++) K += wsum[i];
        g_K[b] = K;
    }
}

// One THREAD per (b,t): build (row, weight) list + write mask output.
// grid = 54 x 256 covers 13632 items with plenty of latency hiding.
__global__ __launch_bounds__(256) void setup_kernel(
    const void* __restrict__ mask,
    const void* __restrict__ keep,
    const float* __restrict__ bj,
    float* __restrict__ out)
{
    int bt = blockIdx.x * blockDim.x + threadIdx.x;
    if (bt >= BB * NT) return;
    int b = bt / NT;
    int t = bt - b * NT;
    int m = g_mode;
    int K = g_K[b];

    bool kb = read_bool_m(keep, bt, m);

    // mask output
    int nidx = (int)floorf((float)t * (512.0f / 426.0f));
    if (nidx > T_IN - 1) nidx = T_IN - 1;
    bool mo = read_bool_m(mask, b * T_IN + nidx, m) && kb;
    out[XPART + (size_t)bt] = mo ? 1.0f : 0.0f;

    // jitter (scale-then-lerp matches reference rounding)
    float jit = 0.0f;
    if (t > 0) {
        float sj = (float)t * (52.0f / 425.0f);
        int ij = (int)floorf(sj);
        if (ij > JF - 2) ij = JF - 2;
        if (ij < 0) ij = 0;
        float fj = sj - (float)ij;
        float j0 = bj[b * JF + ij]     * 0.02f;
        float j1 = bj[b * JF + ij + 1] * 0.02f;
        jit = j0 * (1.0f - fj) + j1 * fj;
    }

    int   rows[8];
    float wv[8];
    int n = 0;

    auto push = [&](int r, float w) {
        for (int i = 0; i < n; i++)
            if (rows[i] == r) { wv[i] += w; return; }
        rows[n] = r; wv[n] = w; n++;
    };
    auto add_x1 = [&](int tau, float c) {
        float s = (float)tau * (511.0f / 425.0f);
        int i0 = (int)floorf(s);
        if (i0 > T_IN - 2) i0 = T_IN - 2;
        if (i0 < 0) i0 = 0;
        float f = s - (float)i0;
        push(i0,     c * (1.0f - f));
        push(i0 + 1, c * f);
    };
    auto add_x2 = [&](int tau, float c) {
        if (read_bool_m(keep, b * NT + tau, m)) {
            add_x1(tau, c);
        } else {
            float s = ((float)tau * (float)(K - 1)) / 425.0f;
            int r0 = (int)floorf(s);
            if (r0 > K - 2) r0 = K - 2;
            if (r0 < 0) r0 = 0;
            float fd = s - (float)r0;
            add_x1(g_kept[b][r0],     c * (1.0f - fd));
            add_x1(g_kept[b][r0 + 1], c * fd);
        }
    };

    if (t == 0) {
        add_x2(0, 1.0f);
    } else {
        add_x2(t,     1.0f + jit);
        add_x2(t - 1, -jit);
    }
    g_n[bt] = n;
    #pragma unroll
    for (int i = 0; i < 8; i++) {
        g_rows[i][bt] = (i < n) ? rows[i] : 0;
        g_w[i][bt]    = (i < n) ? wv[i]   : 0.0f;
    }
}

// Pure streaming (R7 body, proven 58.7us): out[b,t,:] = sum_i w_i * x[b,row_i,:]
// + noise*.01 + spatial*.005. Coalesced chunks e = tid + k*256, 7 independent
// accumulator chains; streaming data (__ldcs/__stcs) bypasses L2 retention.
__global__ __launch_bounds__(256) void fused_kernel(
    const float* __restrict__ x,
    const float* __restrict__ noise,
    const float* __restrict__ sp,
    float* __restrict__ out)
{
    int bt = blockIdx.x;
    int b = bt / NT;

    __shared__ int   srows[8];
    __shared__ float sw[8];
    __shared__ int   snum;

    if (threadIdx.x == 0) snum = g_n[bt];
    if (threadIdx.x < 8) {
        srows[threadIdx.x] = g_rows[threadIdx.x][bt];
        sw[threadIdx.x]    = g_w[threadIdx.x][bt];
    }
    __syncthreads();

    int n = snum;
    const float* xb = x     + (size_t)b * T_IN * NC;
    const float* nz = noise + (size_t)bt * NC;
    const float* sb = sp    + (size_t)b * NC;
    float*       ob = out   + (size_t)bt * NC;

    int tid = threadIdx.x;
    float acc[NCHUNK];
    #pragma unroll
    for (int k = 0; k < NCHUNK; k++) {
        int e = tid + k * 256;
        acc[k] = (e < NC) ? fmaf(__ldcs(nz + e), 0.01f, sb[e] * 0.005f) : 0.0f;
    }

    for (int i = 0; i < n; i++) {
        const float* xr = xb + (size_t)srows[i] * NC;
        float w = sw[i];
        #pragma unroll
        for (int k = 0; k < NCHUNK; k++) {
            int e = tid + k * 256;
            if (e < NC) acc[k] = fmaf(w, __ldg(xr + e), acc[k]);
        }
    }

    #pragma unroll
    for (int k = 0; k < NCHUNK; k++) {
        int e = tid + k * 256;
        if (e < NC) __stcs(ob + e, acc[k]);
    }
}

extern "C" void kernel_launch(void* const* d_in, const int* in_sizes, int n_in,
                              void* d_out, int out_size) {
    const float* x     = (const float*)d_in[0];
    const void*  mask  = d_in[1];
    const void*  keep  = d_in[2];
    const float* bj    = (const float*)d_in[3];
    const float* noise = (const float*)d_in[4];
    const float* sp    = (const float*)d_in[5];
    float* out = (float*)d_out;

    scan_kernel<<<BB, 448>>>(keep);
    setup_kernel<<<(BB * NT + 255) / 256, 256>>>(mask, keep, bj, out);
    fused_kernel<<<BB * NT, 256>>>(x, noise, sp, out);
}

// round 15
// speedup vs baseline: 1.4565x; 1.0067x over previous
#include <cuda_runtime.h>
#include <cstdint>

#define BB 32
#define T_IN 512
#define NT 426
#define NP 213           // NT/2 pairs
#define NC 1629          // 543*3
#define JF 53
#define XPART ((size_t)BB * NT * NC)   // 22,206,528
#define NCHUNK 7         // 7*256 = 1792 >= 1629
#define MAXU 16          // max union rows per pair

// ---- device scratch (SoA for coalesced access) ----
__device__ int   g_mode;
__device__ int   g_K[BB];
__device__ int   g_kept[BB][NT];
__device__ int   g_np[BB * NP];
__device__ int   g_prows[MAXU][BB * NP];
__device__ float g_pw0[MAXU][BB * NP];
__device__ float g_pw1[MAXU][BB * NP];

__device__ __forceinline__ bool read_bool_m(const void* p, int i, int m) {
    if (m == 0) return ((const unsigned char*)p)[i] != 0;
    if (m == 1) return ((const int*)p)[i] != 0;
    return ((const float*)p)[i] != 0.0f;
}

// One block per batch: dtype detect (128-word window, unambiguous across
// uint8/int32/float32 bool layouts) + warp-ballot prefix scan -> kept list.
__global__ __launch_bounds__(448) void scan_kernel(const void* __restrict__ keep) {
    __shared__ int s_bad, s_anyf, s_mode;
    __shared__ int wsum[14];

    int b = blockIdx.x;
    int t = threadIdx.x;                 // 448 threads, 14 warps

    if (t == 0) { s_bad = 0; s_anyf = 0; }
    __syncthreads();
    if (t < 128) {
        unsigned v = ((const unsigned*)keep)[t];
        if (v != 0u && v != 1u) atomicOr(&s_bad, 1);
        if (v == 0x3F800000u)   atomicOr(&s_anyf, 1);
    }
    __syncthreads();
    if (t == 0) {
        s_mode = s_bad ? (s_anyf ? 2 : 0) : 1;
        g_mode = s_mode;                 // all blocks write the same value
    }
    __syncthreads();
    int m = s_mode;

    bool kb = (t < NT) ? read_bool_m(keep, b * NT + t, m) : false;
    unsigned bal = __ballot_sync(0xFFFFFFFFu, kb);
    int lane = t & 31, wid = t >> 5;
    int pre = __popc(bal & ((1u << lane) - 1u));
    if (lane == 0) wsum[wid] = __popc(bal);
    __syncthreads();
    int base = 0;
    for (int i = 0; i < wid; i++) base += wsum[i];
    if (kb) g_kept[b][base + pre] = t;
    if (t == 0) {
        int K = 0;
        for (int i = 0; i < 14; i++) K += wsum[i];
        g_K[b] = K;
    }
}

// One THREAD per (b, pair): build merged (row, w_t0, w_t1) union list for
// t0=2p, t1=2p+1, plus both mask outputs.
__global__ __launch_bounds__(256) void setup_kernel(
    const void* __restrict__ mask,
    const void* __restrict__ keep,
    const float* __restrict__ bj,
    float* __restrict__ out)
{
    int bp = blockIdx.x * blockDim.x + threadIdx.x;
    if (bp >= BB * NP) return;
    int b = bp / NP;
    int p = bp - b * NP;
    int m = g_mode;
    int K = g_K[b];

    int   rowsU[MAXU];
    float w0U[MAXU], w1U[MAXU];
    int nU = 0;

    auto pushU = [&](int r, float w, int which) {
        for (int i = 0; i < nU; i++)
            if (rowsU[i] == r) { if (which) w1U[i] += w; else w0U[i] += w; return; }
        rowsU[nU] = r;
        w0U[nU] = which ? 0.0f : w;
        w1U[nU] = which ? w : 0.0f;
        nU++;
    };
    auto add_x1 = [&](int tau, float c, int which) {
        float s = (float)tau * (511.0f / 425.0f);
        int i0 = (int)floorf(s);
        if (i0 > T_IN - 2) i0 = T_IN - 2;
        if (i0 < 0) i0 = 0;
        float f = s - (float)i0;
        pushU(i0,     c * (1.0f - f), which);
        pushU(i0 + 1, c * f,          which);
    };
    auto add_x2 = [&](int tau, float c, int which) {
        if (read_bool_m(keep, b * NT + tau, m)) {
            add_x1(tau, c, which);
        } else {
            float s = ((float)tau * (float)(K - 1)) / 425.0f;
            int r0 = (int)floorf(s);
            if (r0 > K - 2) r0 = K - 2;
            if (r0 < 0) r0 = 0;
            float fd = s - (float)r0;
            add_x1(g_kept[b][r0],     c * (1.0f - fd), which);
            add_x1(g_kept[b][r0 + 1], c * fd,          which);
        }
    };

    #pragma unroll
    for (int which = 0; which < 2; which++) {
        int t = 2 * p + which;
        int bt = b * NT + t;
        bool kb = read_bool_m(keep, bt, m);

        // mask output
        int nidx = (int)floorf((float)t * (512.0f / 426.0f));
        if (nidx > T_IN - 1) nidx = T_IN - 1;
        bool mo = read_bool_m(mask, b * T_IN + nidx, m) && kb;
        out[XPART + (size_t)bt] = mo ? 1.0f : 0.0f;

        // jitter (scale-then-lerp matches reference rounding)
        float jit = 0.0f;
        if (t > 0) {
            float sj = (float)t * (52.0f / 425.0f);
            int ij = (int)floorf(sj);
            if (ij > JF - 2) ij = JF - 2;
            if (ij < 0) ij = 0;
            float fj = sj - (float)ij;
            float j0 = bj[b * JF + ij]     * 0.02f;
            float j1 = bj[b * JF + ij + 1] * 0.02f;
            jit = j0 * (1.0f - fj) + j1 * fj;
        }

        if (t == 0) {
            add_x2(0, 1.0f, which);
        } else {
            add_x2(t,     1.0f + jit, which);
            add_x2(t - 1, -jit,       which);
        }
    }

    g_np[bp] = nU;
    #pragma unroll
    for (int i = 0; i < MAXU; i++) {
        g_prows[i][bp] = (i < nU) ? rowsU[i] : 0;
        g_pw0[i][bp]   = (i < nU) ? w0U[i]   : 0.0f;
        g_pw1[i][bp]   = (i < nU) ? w1U[i]   : 0.0f;
    }
}

// One block per (b, pair): compute BOTH t outputs in a single pass over the
// union row set. Each x value is loaded once and feeds two FMA chains.
// out[b,t,:] = sum_i w_i * x[b,row_i,:] + noise*.01 + spatial*.005
__global__ __launch_bounds__(256) void fused_kernel(
    const float* __restrict__ x,
    const float* __restrict__ noise,
    const float* __restrict__ sp,
    float* __restrict__ out)
{
    int bp = blockIdx.x;
    int b = bp / NP;
    int t0 = (bp - b * NP) * 2;
    size_t bt0 = (size_t)b * NT + t0;

    __shared__ int   srows[MAXU];
    __shared__ float sw0[MAXU], sw1[MAXU];
    __shared__ int   snum;

    if (threadIdx.x == 0) snum = g_np[bp];
    if (threadIdx.x < MAXU) {
        srows[threadIdx.x] = g_prows[threadIdx.x][bp];
        sw0[threadIdx.x]   = g_pw0[threadIdx.x][bp];
        sw1[threadIdx.x]   = g_pw1[threadIdx.x][bp];
    }
    __syncthreads();

    int n = snum;
    const float* xb  = x     + (size_t)b * T_IN * NC;
    const float* nz0 = noise + bt0 * NC;
    const float* nz1 = nz0 + NC;
    const float* sb  = sp    + (size_t)b * NC;
    float*       ob0 = out   + bt0 * NC;
    float*       ob1 = ob0 + NC;

    int tid = threadIdx.x;
    float acc0[NCHUNK], acc1[NCHUNK];
    #pragma unroll
    for (int k = 0; k < NCHUNK; k++) {
        int e = tid + k * 256;
        float spv = (e < NC) ? sb[e] * 0.005f : 0.0f;
        acc0[k] = (e < NC) ? fmaf(__ldcs(nz0 + e), 0.01f, spv) : 0.0f;
        acc1[k] = (e < NC) ? fmaf(__ldcs(nz1 + e), 0.01f, spv) : 0.0f;
    }

    for (int i = 0; i < n; i++) {
        const float* xr = xb + (size_t)srows[i] * NC;
        float w0 = sw0[i], w1 = sw1[i];
        #pragma unroll
        for (int k = 0; k < NCHUNK; k++) {
            int e = tid + k * 256;
            if (e < NC) {
                float v = __ldg(xr + e);
                acc0[k] = fmaf(w0, v, acc0[k]);
                acc1[k] = fmaf(w1, v, acc1[k]);
            }
        }
    }

    #pragma unroll
    for (int k = 0; k < NCHUNK; k++) {
        int e = tid + k * 256;
        if (e < NC) {
            __stcs(ob0 + e, acc0[k]);
            __stcs(ob1 + e, acc1[k]);
        }
    }
}

extern "C" void kernel_launch(void* const* d_in, const int* in_sizes, int n_in,
                              void* d_out, int out_size) {
    const float* x     = (const float*)d_in[0];
    const void*  mask  = d_in[1];
    const void*  keep  = d_in[2];
    const float* bj    = (const float*)d_in[3];
    const float* noise = (const float*)d_in[4];
    const float* sp    = (const float*)d_in[5];
    float* out = (float*)d_out;

    scan_kernel<<<BB, 448>>>(keep);
    setup_kernel<<<(BB * NP + 255) / 256, 256>>>(mask, keep, bj, out);
    fused_kernel<<<BB * NP, 256>>>(x, noise, sp, out);
}